// round 1
// baseline (speedup 1.0000x reference)
#include <cuda_runtime.h>
#include <math.h>

// Problem constants
#define B_ 16
#define CDIM 256
#define H_ 128
#define W_ 128
#define WS 8
#define HEADS 8
#define DH 32
#define HIDD 1024
#define NTOK 262144   // B * H * W tokens (4096 windows * 64 tokens)

// Scratch (device globals: allocation-free per harness rules)
__device__ float g_tok[67108864];    // [NTOK, 256]
__device__ float g_y[67108864];      // [NTOK, 256]  LN output / final pre-scatter
__device__ float g_qkv[201326592];   // [NTOK, 768]
__device__ float g_o[67108864];      // [NTOK, 256]  attention output
__device__ float g_hid[268435456];   // [NTOK, 1024] MLP hidden

// ---------------------------------------------------------------------------
// Gather: x [B,C,H,W] -> tok [NTOK, C]  (window partition, transpose)
// grid (W/32, C/32, B*H), block (32,8)
// ---------------------------------------------------------------------------
__global__ void __launch_bounds__(256) gather_kernel(const float* __restrict__ x,
                                                     float* __restrict__ tok) {
    __shared__ float tile[32][33];
    const int w0 = blockIdx.x * 32;
    const int c0 = blockIdx.y * 32;
    const int bh = blockIdx.z;
    const int b = bh >> 7, h = bh & 127;
    const int tx = threadIdx.x, ty = threadIdx.y;

    const float* xp = x + ((long long)(b * CDIM + c0)) * (H_ * W_) + h * W_ + w0;
#pragma unroll
    for (int i = 0; i < 4; i++) {
        int c = ty * 4 + i;
        tile[c][tx] = xp[(long long)c * (H_ * W_) + tx];
    }
    __syncthreads();

    const int wy = h >> 3, iy = h & 7;
#pragma unroll
    for (int i = 0; i < 4; i++) {
        int wloc = ty * 4 + i;
        int w = w0 + wloc;
        int wx = w >> 3, ix = w & 7;
        long long r = (((long long)(b * 16 + wy)) * 16 + wx) * 64 + iy * 8 + ix;
        tok[r * CDIM + c0 + tx] = tile[tx][wloc];
    }
}

// ---------------------------------------------------------------------------
// Scatter: tok-layout [NTOK, C] -> x [B,C,H,W]
// ---------------------------------------------------------------------------
__global__ void __launch_bounds__(256) scatter_kernel(const float* __restrict__ tok,
                                                      float* __restrict__ x) {
    __shared__ float tile[32][33];
    const int w0 = blockIdx.x * 32;
    const int c0 = blockIdx.y * 32;
    const int bh = blockIdx.z;
    const int b = bh >> 7, h = bh & 127;
    const int tx = threadIdx.x, ty = threadIdx.y;
    const int wy = h >> 3, iy = h & 7;

#pragma unroll
    for (int i = 0; i < 4; i++) {
        int wloc = ty * 4 + i;
        int w = w0 + wloc;
        int wx = w >> 3, ix = w & 7;
        long long r = (((long long)(b * 16 + wy)) * 16 + wx) * 64 + iy * 8 + ix;
        tile[tx][wloc] = tok[r * CDIM + c0 + tx];
    }
    __syncthreads();

    float* xp = x + ((long long)(b * CDIM + c0)) * (H_ * W_) + h * W_ + w0;
#pragma unroll
    for (int i = 0; i < 4; i++) {
        int c = ty * 4 + i;
        xp[(long long)c * (H_ * W_) + tx] = tile[c][tx];
    }
}

// ---------------------------------------------------------------------------
// LayerNorm over rows of 256. One warp per row, 8 rows per 256-thread block.
// ---------------------------------------------------------------------------
__global__ void __launch_bounds__(256) ln_kernel(const float* __restrict__ A,
                                                 const float* __restrict__ g,
                                                 const float* __restrict__ b,
                                                 float* __restrict__ Y) {
    const long long row = (long long)blockIdx.x * 8 + (threadIdx.x >> 5);
    const int lane = threadIdx.x & 31;
    const float4* ap = (const float4*)(A + row * CDIM);
    float4 v0 = ap[lane];
    float4 v1 = ap[lane + 32];

    float s = v0.x + v0.y + v0.z + v0.w + v1.x + v1.y + v1.z + v1.w;
#pragma unroll
    for (int o = 16; o; o >>= 1) s += __shfl_xor_sync(0xFFFFFFFFu, s, o);
    const float mu = s * (1.0f / 256.0f);

    float q = (v0.x - mu) * (v0.x - mu) + (v0.y - mu) * (v0.y - mu)
            + (v0.z - mu) * (v0.z - mu) + (v0.w - mu) * (v0.w - mu)
            + (v1.x - mu) * (v1.x - mu) + (v1.y - mu) * (v1.y - mu)
            + (v1.z - mu) * (v1.z - mu) + (v1.w - mu) * (v1.w - mu);
#pragma unroll
    for (int o = 16; o; o >>= 1) q += __shfl_xor_sync(0xFFFFFFFFu, q, o);
    const float rinv = rsqrtf(q * (1.0f / 256.0f) + 1e-5f);

    const float4* gp = (const float4*)g;
    const float4* bp = (const float4*)b;
    float4 g0 = gp[lane], g1 = gp[lane + 32];
    float4 b0 = bp[lane], b1 = bp[lane + 32];
    float4 y0, y1;
    y0.x = (v0.x - mu) * rinv * g0.x + b0.x;
    y0.y = (v0.y - mu) * rinv * g0.y + b0.y;
    y0.z = (v0.z - mu) * rinv * g0.z + b0.z;
    y0.w = (v0.w - mu) * rinv * g0.w + b0.w;
    y1.x = (v1.x - mu) * rinv * g1.x + b1.x;
    y1.y = (v1.y - mu) * rinv * g1.y + b1.y;
    y1.z = (v1.z - mu) * rinv * g1.z + b1.z;
    y1.w = (v1.w - mu) * rinv * g1.w + b1.w;
    float4* yp = (float4*)(Y + row * CDIM);
    yp[lane] = y0;
    yp[lane + 32] = y1;
}

// ---------------------------------------------------------------------------
// GEMM: Out[M,N] = A[M,K] * W[N,K]^T + bias  (+ residual R / GELU epilogue)
// BM=128 BN=64 BK=16, 256 threads, 8x4 per-thread tile, double-buffered smem.
// EPI: 0=bias, 1=bias+residual, 2=bias+GELU(exact)
// ---------------------------------------------------------------------------
__device__ __forceinline__ float gelu_exact(float v) {
    return 0.5f * v * (1.0f + erff(v * 0.70710678118654752f));
}

template <int EPI>
__global__ void __launch_bounds__(256) gemm_kernel(const float* __restrict__ A,
                                                   const float* __restrict__ W,
                                                   const float* __restrict__ bias,
                                                   const float* __restrict__ R,
                                                   float* __restrict__ Out,
                                                   int N, int K) {
    __shared__ float As[2][16][128];
    __shared__ float Ws[2][16][64];

    const int tid = threadIdx.x;
    const long long m0 = (long long)blockIdx.x * 128;
    const int n0 = blockIdx.y * 64;
    const int rg = tid >> 4;          // 0..15 -> rows rg*8..rg*8+7
    const int cg = tid & 15;          // 0..15 -> cols cg*4..cg*4+3
    const int lr = tid >> 2;          // 0..63
    const int lc = (tid & 3) * 4;     // 0,4,8,12

    const float* Ap = A + (m0 + lr) * (long long)K + lc;
    const float* Wp = W + (long long)(n0 + lr) * K + lc;

    float4 pa0 = *(const float4*)(Ap);
    float4 pa1 = *(const float4*)(Ap + (long long)64 * K);
    float4 pw  = *(const float4*)(Wp);

    As[0][lc + 0][lr] = pa0.x; As[0][lc + 1][lr] = pa0.y;
    As[0][lc + 2][lr] = pa0.z; As[0][lc + 3][lr] = pa0.w;
    As[0][lc + 0][lr + 64] = pa1.x; As[0][lc + 1][lr + 64] = pa1.y;
    As[0][lc + 2][lr + 64] = pa1.z; As[0][lc + 3][lr + 64] = pa1.w;
    Ws[0][lc + 0][lr] = pw.x; Ws[0][lc + 1][lr] = pw.y;
    Ws[0][lc + 2][lr] = pw.z; Ws[0][lc + 3][lr] = pw.w;
    __syncthreads();

    float acc[8][4];
#pragma unroll
    for (int i = 0; i < 8; i++)
#pragma unroll
        for (int j = 0; j < 4; j++) acc[i][j] = 0.0f;

    const int nkt = K >> 4;
    int buf = 0;
    for (int kt = 0; kt < nkt; kt++) {
        if (kt + 1 < nkt) {
            const int ko = (kt + 1) * 16;
            pa0 = *(const float4*)(Ap + ko);
            pa1 = *(const float4*)(Ap + (long long)64 * K + ko);
            pw  = *(const float4*)(Wp + ko);
        }
#pragma unroll
        for (int k = 0; k < 16; k++) {
            float4 a0 = *(const float4*)&As[buf][k][rg * 8];
            float4 a1 = *(const float4*)&As[buf][k][rg * 8 + 4];
            float4 bv = *(const float4*)&Ws[buf][k][cg * 4];
            float av[8] = {a0.x, a0.y, a0.z, a0.w, a1.x, a1.y, a1.z, a1.w};
            float bw[4] = {bv.x, bv.y, bv.z, bv.w};
#pragma unroll
            for (int i = 0; i < 8; i++)
#pragma unroll
                for (int j = 0; j < 4; j++) acc[i][j] += av[i] * bw[j];
        }
        if (kt + 1 < nkt) {
            const int nb = buf ^ 1;
            As[nb][lc + 0][lr] = pa0.x; As[nb][lc + 1][lr] = pa0.y;
            As[nb][lc + 2][lr] = pa0.z; As[nb][lc + 3][lr] = pa0.w;
            As[nb][lc + 0][lr + 64] = pa1.x; As[nb][lc + 1][lr + 64] = pa1.y;
            As[nb][lc + 2][lr + 64] = pa1.z; As[nb][lc + 3][lr + 64] = pa1.w;
            Ws[nb][lc + 0][lr] = pw.x; Ws[nb][lc + 1][lr] = pw.y;
            Ws[nb][lc + 2][lr] = pw.z; Ws[nb][lc + 3][lr] = pw.w;
            __syncthreads();
            buf = nb;
        }
    }

    const float4 bvec = *(const float4*)&bias[n0 + cg * 4];
#pragma unroll
    for (int i = 0; i < 8; i++) {
        const long long m = m0 + rg * 8 + i;
        float4 r;
        r.x = acc[i][0] + bvec.x;
        r.y = acc[i][1] + bvec.y;
        r.z = acc[i][2] + bvec.z;
        r.w = acc[i][3] + bvec.w;
        if (EPI == 1) {
            float4 rr = *(const float4*)&R[m * (long long)N + n0 + cg * 4];
            r.x += rr.x; r.y += rr.y; r.z += rr.z; r.w += rr.w;
        } else if (EPI == 2) {
            r.x = gelu_exact(r.x);
            r.y = gelu_exact(r.y);
            r.z = gelu_exact(r.z);
            r.w = gelu_exact(r.w);
        }
        *(float4*)&Out[m * (long long)N + n0 + cg * 4] = r;
    }
}

// ---------------------------------------------------------------------------
// Attention: per (window, head) block. T=64, d=32. 128 threads.
// qkv layout per token row (768): [q: s=0 | k: s=1 | v: s=2], col = s*256+h*32+d
// ---------------------------------------------------------------------------
__global__ void __launch_bounds__(128) attn_kernel(const float* __restrict__ qkv,
                                                   float* __restrict__ o) {
    __shared__ float sq[64][33];
    __shared__ float sk[64][33];
    __shared__ float sv[64][33];
    __shared__ float ss[64][65];

    const int tid = threadIdx.x;
    const int n = blockIdx.x >> 3;
    const int head = blockIdx.x & 7;
    const float* base = qkv + (long long)n * 64 * 768 + head * 32;

    {
        const int r0 = tid >> 3;          // 0..15
        const int c4 = (tid & 7) * 4;     // 0..28
#pragma unroll
        for (int it = 0; it < 4; it++) {
            const int r = r0 + it * 16;
            const float* rp = base + (long long)r * 768 + c4;
            float4 qv = *(const float4*)(rp);
            float4 kv = *(const float4*)(rp + 256);
            float4 vv = *(const float4*)(rp + 512);
            sq[r][c4 + 0] = qv.x; sq[r][c4 + 1] = qv.y; sq[r][c4 + 2] = qv.z; sq[r][c4 + 3] = qv.w;
            sk[r][c4 + 0] = kv.x; sk[r][c4 + 1] = kv.y; sk[r][c4 + 2] = kv.z; sk[r][c4 + 3] = kv.w;
            sv[r][c4 + 0] = vv.x; sv[r][c4 + 1] = vv.y; sv[r][c4 + 2] = vv.z; sv[r][c4 + 3] = vv.w;
        }
    }
    __syncthreads();

    // scores: each thread computes a 4x8 tile of the 64x64 score matrix
    {
        const int rg = tid >> 3;   // 0..15 -> rows rg*4..+4
        const int cgg = tid & 7;   // 0..7  -> cols cgg*8..+8
        float acc[4][8];
#pragma unroll
        for (int i = 0; i < 4; i++)
#pragma unroll
            for (int j = 0; j < 8; j++) acc[i][j] = 0.0f;

#pragma unroll 4
        for (int kk = 0; kk < 32; kk++) {
            float a[4], bb[8];
#pragma unroll
            for (int i = 0; i < 4; i++) a[i] = sq[rg * 4 + i][kk];
#pragma unroll
            for (int j = 0; j < 8; j++) bb[j] = sk[cgg * 8 + j][kk];
#pragma unroll
            for (int i = 0; i < 4; i++)
#pragma unroll
                for (int j = 0; j < 8; j++) acc[i][j] += a[i] * bb[j];
        }
        const float scale = 0.17677669529663689f;  // 1/sqrt(32)
#pragma unroll
        for (int i = 0; i < 4; i++)
#pragma unroll
            for (int j = 0; j < 8; j++)
                ss[rg * 4 + i][cgg * 8 + j] = acc[i][j] * scale;
    }
    __syncthreads();

    // softmax: one thread per row
    if (tid < 64) {
        float mx = -1e30f;
#pragma unroll 8
        for (int j = 0; j < 64; j++) mx = fmaxf(mx, ss[tid][j]);
        float sum = 0.0f;
#pragma unroll 8
        for (int j = 0; j < 64; j++) {
            float e = expf(ss[tid][j] - mx);
            ss[tid][j] = e;
            sum += e;
        }
        const float inv = 1.0f / sum;
#pragma unroll 8
        for (int j = 0; j < 64; j++) ss[tid][j] *= inv;
    }
    __syncthreads();

    // o = attn @ v : each thread computes a 4x4 tile of [64, 32]
    {
        const int rg = tid >> 3;       // rows rg*4..+4
        const int cgo = tid & 7;       // cols cgo*4..+4
        float acc[4][4];
#pragma unroll
        for (int i = 0; i < 4; i++)
#pragma unroll
            for (int j = 0; j < 4; j++) acc[i][j] = 0.0f;

#pragma unroll 4
        for (int kk = 0; kk < 64; kk++) {
            float a[4], bb[4];
#pragma unroll
            for (int i = 0; i < 4; i++) a[i] = ss[rg * 4 + i][kk];
#pragma unroll
            for (int j = 0; j < 4; j++) bb[j] = sv[kk][cgo * 4 + j];
#pragma unroll
            for (int i = 0; i < 4; i++)
#pragma unroll
                for (int j = 0; j < 4; j++) acc[i][j] += a[i] * bb[j];
        }
#pragma unroll
        for (int i = 0; i < 4; i++) {
            float4 r;
            r.x = acc[i][0]; r.y = acc[i][1]; r.z = acc[i][2]; r.w = acc[i][3];
            *(float4*)&o[((long long)n * 64 + rg * 4 + i) * CDIM + head * 32 + cgo * 4] = r;
        }
    }
}

// ---------------------------------------------------------------------------
// Launch
// ---------------------------------------------------------------------------
extern "C" void kernel_launch(void* const* d_in, const int* in_sizes, int n_in,
                              void* d_out, int out_size) {
    const float* x      = (const float*)d_in[0];
    const float* qkv_w  = (const float*)d_in[1];
    const float* qkv_b  = (const float*)d_in[2];
    const float* proj_w = (const float*)d_in[3];
    const float* proj_b = (const float*)d_in[4];
    const float* n1_g   = (const float*)d_in[5];
    const float* n1_b   = (const float*)d_in[6];
    const float* n2_g   = (const float*)d_in[7];
    const float* n2_b   = (const float*)d_in[8];
    const float* fc1_w  = (const float*)d_in[9];
    const float* fc1_b  = (const float*)d_in[10];
    const float* fc2_w  = (const float*)d_in[11];
    const float* fc2_b  = (const float*)d_in[12];
    float* out = (float*)d_out;

    float *tok, *y, *qkv, *o, *hid;
    cudaGetSymbolAddress((void**)&tok, g_tok);
    cudaGetSymbolAddress((void**)&y, g_y);
    cudaGetSymbolAddress((void**)&qkv, g_qkv);
    cudaGetSymbolAddress((void**)&o, g_o);
    cudaGetSymbolAddress((void**)&hid, g_hid);

    const dim3 tb(32, 8);
    const dim3 tg(W_ / 32, CDIM / 32, B_ * H_);

    // 1. window partition
    gather_kernel<<<tg, tb>>>(x, tok);
    // 2. LN1
    ln_kernel<<<NTOK / 8, 256>>>(tok, n1_g, n1_b, y);
    // 3. QKV gemm: [NTOK,256] x [768,256]^T
    gemm_kernel<0><<<dim3(NTOK / 128, 768 / 64), 256>>>(y, qkv_w, qkv_b, nullptr, qkv, 768, 256);
    // 4. windowed attention
    attn_kernel<<<4096 * 8, 128>>>(qkv, o);
    // 5. proj gemm + residual -> tok
    gemm_kernel<1><<<dim3(NTOK / 128, 256 / 64), 256>>>(o, proj_w, proj_b, tok, tok, 256, 256);
    // 6. LN2
    ln_kernel<<<NTOK / 8, 256>>>(tok, n2_g, n2_b, y);
    // 7. fc1 gemm + GELU
    gemm_kernel<2><<<dim3(NTOK / 128, 1024 / 64), 256>>>(y, fc1_w, fc1_b, nullptr, hid, 1024, 256);
    // 8. fc2 gemm + residual -> y
    gemm_kernel<1><<<dim3(NTOK / 128, 256 / 64), 256>>>(hid, fc2_w, fc2_b, tok, y, 256, 1024);
    // 9. un-partition to NCHW
    scatter_kernel<<<tg, tb>>>(y, out);
}

// round 3
// speedup vs baseline: 1.9211x; 1.9211x over previous
#include <cuda_runtime.h>
#include <math.h>
#include <cstdint>

// Problem constants
#define B_ 16
#define CDIM 256
#define H_ 128
#define W_ 128
#define NTOK 262144   // B*H*W tokens

// Scratch (device globals)
__device__ float g_tok[67108864];    // [NTOK, 256]
__device__ float g_y[67108864];      // [NTOK, 256]
__device__ float g_qkv[201326592];   // [NTOK, 768]
__device__ float g_o[67108864];      // [NTOK, 256]
__device__ float g_hid[268435456];   // [NTOK, 1024]

__device__ __forceinline__ uint32_t f32_tf32(float v) {
    uint32_t u;
    asm("cvt.rna.tf32.f32 %0, %1;" : "=r"(u) : "f"(v));
    return u;
}

__device__ __forceinline__ float gelu_exact(float v) {
    return 0.5f * v * (1.0f + erff(v * 0.70710678118654752f));
}

// ===========================================================================
// TF32 mma.sync GEMM: Out[M,N] = A[M,K] * W[N,K]^T + bias (+ epilogue)
// CTA tile 128x128, K-chunk 32. 8 warps -> warp tile 64x32.
// SMEM: XOR swizzle col^=4*(row&7) on 32-float rows (conflict-free).
// EPI: 0=bias, 1=bias+residual, 2=bias+GELU
// ===========================================================================
template <int EPI>
__global__ void __launch_bounds__(256) mma_gemm(const float* __restrict__ A,
                                                const float* __restrict__ W,
                                                const float* __restrict__ bias,
                                                const float* __restrict__ R,
                                                float* __restrict__ Out,
                                                int N, int K) {
    __shared__ uint32_t As[128 * 32];
    __shared__ uint32_t Bs[128 * 32];

    const int tid = threadIdx.x;
    const int wid = tid >> 5;
    const int lane = tid & 31;
    const long long m0 = (long long)blockIdx.x * 128;
    const int n0 = blockIdx.y * 128;

    const int wm = (wid >> 2) * 64;   // warp m offset within CTA tile
    const int wn = (wid & 3) * 32;    // warp n offset

    const int lm = lane >> 2;         // 0..7
    const int lk = lane & 3;          // 0..3

    // global load mapping: row r = tid>>1, cols (tid&1)*16 + 4j
    const int gr = tid >> 1;
    const int gc = (tid & 1) * 16;
    const int swr = (gr & 7) * 4;

    float d[4][4][4];
#pragma unroll
    for (int i = 0; i < 4; i++)
#pragma unroll
        for (int j = 0; j < 4; j++)
#pragma unroll
            for (int q = 0; q < 4; q++) d[i][j][q] = 0.0f;

    const int KT = K >> 5;
    for (int kt = 0; kt < KT; kt++) {
        __syncthreads();
        // ---- load A tile [128 x 32] and B tile [128 x 32], cvt to tf32 ----
        {
            const float4* ap = (const float4*)(A + (m0 + gr) * (long long)K + kt * 32 + gc);
            const float4* bp = (const float4*)(W + (long long)(n0 + gr) * K + kt * 32 + gc);
#pragma unroll
            for (int j = 0; j < 4; j++) {
                float4 va = ap[j];
                float4 vb = bp[j];
                uint4 ta, tb;
                ta.x = f32_tf32(va.x); ta.y = f32_tf32(va.y);
                ta.z = f32_tf32(va.z); ta.w = f32_tf32(va.w);
                tb.x = f32_tf32(vb.x); tb.y = f32_tf32(vb.y);
                tb.z = f32_tf32(vb.z); tb.w = f32_tf32(vb.w);
                const int c = (gc + j * 4) ^ swr;
                *(uint4*)&As[gr * 32 + c] = ta;
                *(uint4*)&Bs[gr * 32 + c] = tb;
            }
        }
        __syncthreads();

        // ---- compute: 4 k8-steps ----
#pragma unroll
        for (int kk = 0; kk < 32; kk += 8) {
            uint32_t a[4][4];
#pragma unroll
            for (int mf = 0; mf < 4; mf++) {
                const int m = wm + mf * 16 + lm;
                const int sw = (m & 7) * 4;
                const int c0 = (kk + lk) ^ sw;
                const int c1 = (kk + 4 + lk) ^ sw;
                a[mf][0] = As[m * 32 + c0];
                a[mf][1] = As[(m + 8) * 32 + c0];
                a[mf][2] = As[m * 32 + c1];
                a[mf][3] = As[(m + 8) * 32 + c1];
            }
            uint32_t b[4][2];
#pragma unroll
            for (int nf = 0; nf < 4; nf++) {
                const int n = wn + nf * 8 + lm;
                const int sw = (n & 7) * 4;
                b[nf][0] = Bs[n * 32 + ((kk + lk) ^ sw)];
                b[nf][1] = Bs[n * 32 + ((kk + 4 + lk) ^ sw)];
            }
#pragma unroll
            for (int mf = 0; mf < 4; mf++)
#pragma unroll
                for (int nf = 0; nf < 4; nf++) {
                    asm volatile(
                        "mma.sync.aligned.m16n8k8.row.col.f32.tf32.tf32.f32 "
                        "{%0,%1,%2,%3}, {%4,%5,%6,%7}, {%8,%9}, {%0,%1,%2,%3};"
                        : "+f"(d[mf][nf][0]), "+f"(d[mf][nf][1]),
                          "+f"(d[mf][nf][2]), "+f"(d[mf][nf][3])
                        : "r"(a[mf][0]), "r"(a[mf][1]), "r"(a[mf][2]), "r"(a[mf][3]),
                          "r"(b[nf][0]), "r"(b[nf][1]));
                }
        }
    }

    // ---- epilogue ----
#pragma unroll
    for (int nf = 0; nf < 4; nf++) {
        const int gcol = n0 + wn + nf * 8 + 2 * lk;
        const float2 bv = *(const float2*)&bias[gcol];
#pragma unroll
        for (int mf = 0; mf < 4; mf++) {
            const long long row = m0 + wm + mf * 16 + lm;
            float2 v0, v1;
            v0.x = d[mf][nf][0] + bv.x;
            v0.y = d[mf][nf][1] + bv.y;
            v1.x = d[mf][nf][2] + bv.x;
            v1.y = d[mf][nf][3] + bv.y;
            if (EPI == 1) {
                float2 r0 = *(const float2*)&R[row * (long long)N + gcol];
                float2 r1 = *(const float2*)&R[(row + 8) * (long long)N + gcol];
                v0.x += r0.x; v0.y += r0.y;
                v1.x += r1.x; v1.y += r1.y;
            } else if (EPI == 2) {
                v0.x = gelu_exact(v0.x); v0.y = gelu_exact(v0.y);
                v1.x = gelu_exact(v1.x); v1.y = gelu_exact(v1.y);
            }
            *(float2*)&Out[row * (long long)N + gcol] = v0;
            *(float2*)&Out[(row + 8) * (long long)N + gcol] = v1;
        }
    }
}

// ===========================================================================
// Gather / Scatter / LayerNorm / Attention (R1, unchanged)
// ===========================================================================
__global__ void __launch_bounds__(256) gather_kernel(const float* __restrict__ x,
                                                     float* __restrict__ tok) {
    __shared__ float tile[32][33];
    const int w0 = blockIdx.x * 32;
    const int c0 = blockIdx.y * 32;
    const int bh = blockIdx.z;
    const int b = bh >> 7, h = bh & 127;
    const int tx = threadIdx.x, ty = threadIdx.y;

    const float* xp = x + ((long long)(b * CDIM + c0)) * (H_ * W_) + h * W_ + w0;
#pragma unroll
    for (int i = 0; i < 4; i++) {
        int c = ty * 4 + i;
        tile[c][tx] = xp[(long long)c * (H_ * W_) + tx];
    }
    __syncthreads();

    const int wy = h >> 3, iy = h & 7;
#pragma unroll
    for (int i = 0; i < 4; i++) {
        int wloc = ty * 4 + i;
        int w = w0 + wloc;
        int wx = w >> 3, ix = w & 7;
        long long r = (((long long)(b * 16 + wy)) * 16 + wx) * 64 + iy * 8 + ix;
        tok[r * CDIM + c0 + tx] = tile[tx][wloc];
    }
}

__global__ void __launch_bounds__(256) scatter_kernel(const float* __restrict__ tok,
                                                      float* __restrict__ x) {
    __shared__ float tile[32][33];
    const int w0 = blockIdx.x * 32;
    const int c0 = blockIdx.y * 32;
    const int bh = blockIdx.z;
    const int b = bh >> 7, h = bh & 127;
    const int tx = threadIdx.x, ty = threadIdx.y;
    const int wy = h >> 3, iy = h & 7;

#pragma unroll
    for (int i = 0; i < 4; i++) {
        int wloc = ty * 4 + i;
        int w = w0 + wloc;
        int wx = w >> 3, ix = w & 7;
        long long r = (((long long)(b * 16 + wy)) * 16 + wx) * 64 + iy * 8 + ix;
        tile[tx][wloc] = tok[r * CDIM + c0 + tx];
    }
    __syncthreads();

    float* xp = x + ((long long)(b * CDIM + c0)) * (H_ * W_) + h * W_ + w0;
#pragma unroll
    for (int i = 0; i < 4; i++) {
        int c = ty * 4 + i;
        xp[(long long)c * (H_ * W_) + tx] = tile[c][tx];
    }
}

__global__ void __launch_bounds__(256) ln_kernel(const float* __restrict__ A,
                                                 const float* __restrict__ g,
                                                 const float* __restrict__ b,
                                                 float* __restrict__ Y) {
    const long long row = (long long)blockIdx.x * 8 + (threadIdx.x >> 5);
    const int lane = threadIdx.x & 31;
    const float4* ap = (const float4*)(A + row * CDIM);
    float4 v0 = ap[lane];
    float4 v1 = ap[lane + 32];

    float s = v0.x + v0.y + v0.z + v0.w + v1.x + v1.y + v1.z + v1.w;
#pragma unroll
    for (int o = 16; o; o >>= 1) s += __shfl_xor_sync(0xFFFFFFFFu, s, o);
    const float mu = s * (1.0f / 256.0f);

    float q = (v0.x - mu) * (v0.x - mu) + (v0.y - mu) * (v0.y - mu)
            + (v0.z - mu) * (v0.z - mu) + (v0.w - mu) * (v0.w - mu)
            + (v1.x - mu) * (v1.x - mu) + (v1.y - mu) * (v1.y - mu)
            + (v1.z - mu) * (v1.z - mu) + (v1.w - mu) * (v1.w - mu);
#pragma unroll
    for (int o = 16; o; o >>= 1) q += __shfl_xor_sync(0xFFFFFFFFu, q, o);
    const float rinv = rsqrtf(q * (1.0f / 256.0f) + 1e-5f);

    const float4* gp = (const float4*)g;
    const float4* bp = (const float4*)b;
    float4 g0 = gp[lane], g1 = gp[lane + 32];
    float4 b0 = bp[lane], b1 = bp[lane + 32];
    float4 y0, y1;
    y0.x = (v0.x - mu) * rinv * g0.x + b0.x;
    y0.y = (v0.y - mu) * rinv * g0.y + b0.y;
    y0.z = (v0.z - mu) * rinv * g0.z + b0.z;
    y0.w = (v0.w - mu) * rinv * g0.w + b0.w;
    y1.x = (v1.x - mu) * rinv * g1.x + b1.x;
    y1.y = (v1.y - mu) * rinv * g1.y + b1.y;
    y1.z = (v1.z - mu) * rinv * g1.z + b1.z;
    y1.w = (v1.w - mu) * rinv * g1.w + b1.w;
    float4* yp = (float4*)(Y + row * CDIM);
    yp[lane] = y0;
    yp[lane + 32] = y1;
}

__global__ void __launch_bounds__(128) attn_kernel(const float* __restrict__ qkv,
                                                   float* __restrict__ o) {
    __shared__ float sq[64][33];
    __shared__ float sk[64][33];
    __shared__ float sv[64][33];
    __shared__ float ss[64][65];

    const int tid = threadIdx.x;
    const int n = blockIdx.x >> 3;
    const int head = blockIdx.x & 7;
    const float* base = qkv + (long long)n * 64 * 768 + head * 32;

    {
        const int r0 = tid >> 3;
        const int c4 = (tid & 7) * 4;
#pragma unroll
        for (int it = 0; it < 4; it++) {
            const int r = r0 + it * 16;
            const float* rp = base + (long long)r * 768 + c4;
            float4 qv = *(const float4*)(rp);
            float4 kv = *(const float4*)(rp + 256);
            float4 vv = *(const float4*)(rp + 512);
            sq[r][c4 + 0] = qv.x; sq[r][c4 + 1] = qv.y; sq[r][c4 + 2] = qv.z; sq[r][c4 + 3] = qv.w;
            sk[r][c4 + 0] = kv.x; sk[r][c4 + 1] = kv.y; sk[r][c4 + 2] = kv.z; sk[r][c4 + 3] = kv.w;
            sv[r][c4 + 0] = vv.x; sv[r][c4 + 1] = vv.y; sv[r][c4 + 2] = vv.z; sv[r][c4 + 3] = vv.w;
        }
    }
    __syncthreads();

    {
        const int rg = tid >> 3;
        const int cgg = tid & 7;
        float acc[4][8];
#pragma unroll
        for (int i = 0; i < 4; i++)
#pragma unroll
            for (int j = 0; j < 8; j++) acc[i][j] = 0.0f;

#pragma unroll 4
        for (int kk = 0; kk < 32; kk++) {
            float a[4], bb[8];
#pragma unroll
            for (int i = 0; i < 4; i++) a[i] = sq[rg * 4 + i][kk];
#pragma unroll
            for (int j = 0; j < 8; j++) bb[j] = sk[cgg * 8 + j][kk];
#pragma unroll
            for (int i = 0; i < 4; i++)
#pragma unroll
                for (int j = 0; j < 8; j++) acc[i][j] += a[i] * bb[j];
        }
        const float scale = 0.17677669529663689f;
#pragma unroll
        for (int i = 0; i < 4; i++)
#pragma unroll
            for (int j = 0; j < 8; j++)
                ss[rg * 4 + i][cgg * 8 + j] = acc[i][j] * scale;
    }
    __syncthreads();

    if (tid < 64) {
        float mx = -1e30f;
#pragma unroll 8
        for (int j = 0; j < 64; j++) mx = fmaxf(mx, ss[tid][j]);
        float sum = 0.0f;
#pragma unroll 8
        for (int j = 0; j < 64; j++) {
            float e = expf(ss[tid][j] - mx);
            ss[tid][j] = e;
            sum += e;
        }
        const float inv = 1.0f / sum;
#pragma unroll 8
        for (int j = 0; j < 64; j++) ss[tid][j] *= inv;
    }
    __syncthreads();

    {
        const int rg = tid >> 3;
        const int cgo = tid & 7;
        float acc[4][4];
#pragma unroll
        for (int i = 0; i < 4; i++)
#pragma unroll
            for (int j = 0; j < 4; j++) acc[i][j] = 0.0f;

#pragma unroll 4
        for (int kk = 0; kk < 64; kk++) {
            float a[4], bb[4];
#pragma unroll
            for (int i = 0; i < 4; i++) a[i] = ss[rg * 4 + i][kk];
#pragma unroll
            for (int j = 0; j < 4; j++) bb[j] = sv[kk][cgo * 4 + j];
#pragma unroll
            for (int i = 0; i < 4; i++)
#pragma unroll
                for (int j = 0; j < 4; j++) acc[i][j] += a[i] * bb[j];
        }
#pragma unroll
        for (int i = 0; i < 4; i++) {
            float4 r;
            r.x = acc[i][0]; r.y = acc[i][1]; r.z = acc[i][2]; r.w = acc[i][3];
            *(float4*)&o[((long long)n * 64 + rg * 4 + i) * CDIM + head * 32 + cgo * 4] = r;
        }
    }
}

// ===========================================================================
// Launch
// ===========================================================================
extern "C" void kernel_launch(void* const* d_in, const int* in_sizes, int n_in,
                              void* d_out, int out_size) {
    const float* x      = (const float*)d_in[0];
    const float* qkv_w  = (const float*)d_in[1];
    const float* qkv_b  = (const float*)d_in[2];
    const float* proj_w = (const float*)d_in[3];
    const float* proj_b = (const float*)d_in[4];
    const float* n1_g   = (const float*)d_in[5];
    const float* n1_b   = (const float*)d_in[6];
    const float* n2_g   = (const float*)d_in[7];
    const float* n2_b   = (const float*)d_in[8];
    const float* fc1_w  = (const float*)d_in[9];
    const float* fc1_b  = (const float*)d_in[10];
    const float* fc2_w  = (const float*)d_in[11];
    const float* fc2_b  = (const float*)d_in[12];
    float* out = (float*)d_out;

    float *tok, *y, *qkv, *o, *hid;
    cudaGetSymbolAddress((void**)&tok, g_tok);
    cudaGetSymbolAddress((void**)&y, g_y);
    cudaGetSymbolAddress((void**)&qkv, g_qkv);
    cudaGetSymbolAddress((void**)&o, g_o);
    cudaGetSymbolAddress((void**)&hid, g_hid);

    const dim3 tb(32, 8);
    const dim3 tg(W_ / 32, CDIM / 32, B_ * H_);
    const int MT = NTOK / 128;  // 2048 M-tiles

    // 1. window partition
    gather_kernel<<<tg, tb>>>(x, tok);
    // 2. LN1
    ln_kernel<<<NTOK / 8, 256>>>(tok, n1_g, n1_b, y);
    // 3. QKV gemm (tf32 mma.sync)
    mma_gemm<0><<<dim3(MT, 768 / 128), 256>>>(y, qkv_w, qkv_b, nullptr, qkv, 768, 256);
    // 4. windowed attention
    attn_kernel<<<4096 * 8, 128>>>(qkv, o);
    // 5. proj gemm + residual -> tok
    mma_gemm<1><<<dim3(MT, 256 / 128), 256>>>(o, proj_w, proj_b, tok, tok, 256, 256);
    // 6. LN2
    ln_kernel<<<NTOK / 8, 256>>>(tok, n2_g, n2_b, y);
    // 7. fc1 gemm + GELU
    mma_gemm<2><<<dim3(MT, 1024 / 128), 256>>>(y, fc1_w, fc1_b, nullptr, hid, 1024, 256);
    // 8. fc2 gemm + residual -> y
    mma_gemm<1><<<dim3(MT, 256 / 128), 256>>>(hid, fc2_w, fc2_b, tok, y, 256, 1024);
    // 9. un-partition
    scatter_kernel<<<tg, tb>>>(y, out);
}